// round 6
// baseline (speedup 1.0000x reference)
#include <cuda_runtime.h>
#include <cuda_fp16.h>
#include <cstdint>
#include <cstddef>

#define B_ 64
#define S_ 512
#define E_ 512
#define H_ 1024
#define NCTA 96

// ---------------- device scratch ---------------------------------------------
__device__ __half g_Wih0T[(size_t)H_ * E_];   // [n][e]
__device__ __half g_Whh0T[(size_t)H_ * H_];   // [n][k]
__device__ __half g_Wih1T[(size_t)H_ * H_];
__device__ __half g_Whh1T[(size_t)H_ * H_];
__device__ float  g_bias0[H_];
__device__ float  g_bias1[H_];
__device__ __half g_X0[(size_t)S_ * B_ * H_]; // [t][b][n]
__device__ __half g_h0[2][B_ * H_];
__device__ __half g_h1[2][B_ * H_];
__device__ float  g_h0f[B_ * H_];
__device__ int    g_is64;

// accumulators for K-split partial sums: [layer][slot][nt][64*128]
__device__ float             g_accum[2][2][8][B_ * 128];
__device__ volatile unsigned g_flag[NCTA];     // producer stamped flags
__device__ volatile unsigned g_cons[2][8];     // finisher consumed stamps
__device__ unsigned          g_r0, g_r1;       // h0/h1 ready counters (8 inc/step)
__device__ unsigned          g_h0rd[2];        // h0 read-done, indexed by step parity
__device__ unsigned          g_h1rd[2];        // h1 read-done, indexed by step parity

// ---------------- helpers ----------------------------------------------------
__device__ __forceinline__ void mma16816(float* c, const uint32_t* a, const uint32_t* b) {
    asm volatile(
        "mma.sync.aligned.m16n8k16.row.col.f32.f16.f16.f32 "
        "{%0,%1,%2,%3}, {%4,%5,%6,%7}, {%8,%9}, {%0,%1,%2,%3};\n"
        : "+f"(c[0]), "+f"(c[1]), "+f"(c[2]), "+f"(c[3])
        : "r"(a[0]), "r"(a[1]), "r"(a[2]), "r"(a[3]), "r"(b[0]), "r"(b[1]));
}
__device__ __forceinline__ void ldsm4(uint32_t* r, const void* p) {
    uint32_t a = (uint32_t)__cvta_generic_to_shared(p);
    asm volatile("ldmatrix.sync.aligned.m8n8.x4.shared.b16 {%0,%1,%2,%3}, [%4];"
                 : "=r"(r[0]), "=r"(r[1]), "=r"(r[2]), "=r"(r[3]) : "r"(a));
}
__device__ __forceinline__ void cp_async16(void* sptr, const void* gptr) {
    unsigned s = (unsigned)__cvta_generic_to_shared(sptr);
    asm volatile("cp.async.cg.shared.global [%0], [%1], 16;\n" :: "r"(s), "l"(gptr));
}
__device__ __forceinline__ void cp_commit() { asm volatile("cp.async.commit_group;\n"); }
template <int N>
__device__ __forceinline__ void cp_wait() { asm volatile("cp.async.wait_group %0;\n" :: "n"(N)); }
__device__ __forceinline__ void redadd(float* p, float v) {
    asm volatile("red.global.add.f32 [%0], %1;\n" :: "l"(p), "f"(v) : "memory");
}
__device__ __forceinline__ void spin_ge(volatile unsigned* p, unsigned target) {
    while (*p < target) { __nanosleep(20); }
}

// ---------------- setup kernels -----------------------------------------------
__global__ void k_detect(const int* src32) {
    __shared__ int bad;
    if (threadIdx.x == 0) bad = 0;
    __syncthreads();
    if (src32[2 * threadIdx.x + 1] != 0) atomicExch(&bad, 1);
    __syncthreads();
    if (threadIdx.x == 0) g_is64 = bad ? 0 : 1;
}

__global__ void k_convT(const float* __restrict__ w, int which) {
    __half* dst; int K;
    switch (which) {
        case 0:  dst = g_Wih0T; K = E_; break;
        case 1:  dst = g_Whh0T; K = H_; break;
        case 2:  dst = g_Wih1T; K = H_; break;
        default: dst = g_Whh1T; K = H_; break;
    }
    size_t total = (size_t)K * H_;
    for (size_t i = (size_t)blockIdx.x * blockDim.x + threadIdx.x; i < total;
         i += (size_t)gridDim.x * blockDim.x) {
        size_t n = i / (size_t)K;
        size_t k = i - n * (size_t)K;
        dst[i] = __float2half(w[k * H_ + n]);
    }
}

__global__ void k_bias(const float* bih0, const float* bhh0,
                       const float* bih1, const float* bhh1) {
    int i = blockIdx.x * blockDim.x + threadIdx.x;
    if (i < H_) {
        g_bias0[i] = bih0[i] + bhh0[i];
        g_bias1[i] = bih1[i] + bhh1[i];
    }
}

// ---------------- phase 1: X0 = emb[src] @ W_ih0 -----------------------------
__global__ void __launch_bounds__(256) k_phase1(const void* srcv, const float* __restrict__ emb) {
    __shared__ __half sA[64][72];
    __shared__ __half sB[64][72];
    __shared__ int    sSrc[64];

    const int* s32 = (const int*)srcv;
    int tid = threadIdx.x;
    int nt = blockIdx.x;
    int mt = blockIdx.y;
    int n0 = nt * 64;

    if (tid < 64) {
        int idx = tid * S_ + mt;
        sSrc[tid] = g_is64 ? s32[2 * idx] : s32[idx];
    }
    __syncthreads();

    int warp = tid >> 5, lane = tid & 31;
    int g = lane >> 2, tg = lane & 3;
    int wm = warp >> 2, wn = warp & 3;

    float acc[2][2][4];
#pragma unroll
    for (int i = 0; i < 2; i++)
#pragma unroll
        for (int j = 0; j < 2; j++)
#pragma unroll
            for (int q = 0; q < 4; q++) acc[i][j][q] = 0.f;

    for (int kc = 0; kc < E_; kc += 64) {
        __syncthreads();
#pragma unroll
        for (int it = 0; it < 4; it++) {
            int idx = tid + it * 256;
            int r = idx >> 4, c4 = idx & 15;
            float4 v = *(const float4*)(emb + (size_t)sSrc[r] * E_ + kc + c4 * 4);
            *(__half2*)&sA[r][c4 * 4]     = __floats2half2_rn(v.x, v.y);
            *(__half2*)&sA[r][c4 * 4 + 2] = __floats2half2_rn(v.z, v.w);
        }
#pragma unroll
        for (int it = 0; it < 2; it++) {
            int idx = tid + it * 256;
            int r = idx >> 3, c8 = idx & 7;
            *(uint4*)&sB[r][c8 * 8] =
                *(const uint4*)(g_Wih0T + (size_t)(n0 + r) * E_ + kc + c8 * 8);
        }
        __syncthreads();
#pragma unroll
        for (int kk = 0; kk < 64; kk += 16) {
            uint32_t af[2][4], bf[2][2];
#pragma unroll
            for (int ms = 0; ms < 2; ms++) {
                int rb = wm * 32 + ms * 16;
                af[ms][0] = *(const uint32_t*)&sA[rb + g][kk + tg * 2];
                af[ms][1] = *(const uint32_t*)&sA[rb + g + 8][kk + tg * 2];
                af[ms][2] = *(const uint32_t*)&sA[rb + g][kk + tg * 2 + 8];
                af[ms][3] = *(const uint32_t*)&sA[rb + g + 8][kk + tg * 2 + 8];
            }
#pragma unroll
            for (int ns = 0; ns < 2; ns++) {
                int nc = wn * 16 + ns * 8 + g;
                bf[ns][0] = *(const uint32_t*)&sB[nc][kk + tg * 2];
                bf[ns][1] = *(const uint32_t*)&sB[nc][kk + tg * 2 + 8];
            }
#pragma unroll
            for (int ms = 0; ms < 2; ms++)
#pragma unroll
                for (int ns = 0; ns < 2; ns++) mma16816(acc[ms][ns], af[ms], bf[ns]);
        }
    }
#pragma unroll
    for (int ms = 0; ms < 2; ms++)
#pragma unroll
        for (int ns = 0; ns < 2; ns++) {
            int n = n0 + wn * 16 + ns * 8 + tg * 2;
#pragma unroll
            for (int hh = 0; hh < 2; hh++) {
                int row = wm * 32 + ms * 16 + g + hh * 8;
                size_t m = (size_t)mt * 64 + row;
                *(__half2*)&g_X0[m * H_ + n] =
                    __floats2half2_rn(acc[ms][ns][hh * 2], acc[ms][ns][hh * 2 + 1]);
            }
        }
}

// ---------------- init: h state, sync state, zero accum -----------------------
__global__ void k_init() {
    int i = blockIdx.x * blockDim.x + threadIdx.x;
    if (i < NCTA) g_flag[i] = 0u;
    if (i == 0) {
        g_r0 = 0u; g_r1 = 0u;
        g_h0rd[0] = 0u; g_h0rd[1] = 0u;
        g_h1rd[0] = 0u; g_h1rd[1] = 0u;
    }
    if (i < 16) g_cons[i >> 3][i & 7] = 0u;
    // zero accumulators: 2*2*8*8192 = 262144 floats (65536 threads x 4)
    float* acc = &g_accum[0][0][0][0];
#pragma unroll
    for (int q = 0; q < 4; q++) acc[i + q * (B_ * H_)] = 0.f;
    if (i < B_ * H_) {
        int n = i & (H_ - 1);
        float h = tanhf(__half2float(g_X0[i]) + g_bias0[n]);
        g_h0[0][i] = __float2half(h);
        g_h0f[i] = h;
        g_h1[0][i] = __float2half(0.f);
    }
}

// ---------------- persistent recurrent kernel --------------------------------
// 96 CTAs x 128 threads. grp = cta/32: 0 -> h0@Whh0, 1 -> h0@Wih1, 2 -> h1@Whh1.
// Within group: nt = (cta&31)>>2 (N-tile of 128), kq = cta&3 (K-quarter of 256).
// kq==0 of grp0/grp2 are finishers; all others red.add partials into g_accum.
#define SA_STRIDE 72
#define SA_CHUNK (64 * SA_STRIDE)
#define BFRAG_BYTES (16 * 16 * 32 * 8)
#define DYN_SMEM (BFRAG_BYTES + 4 * SA_CHUNK * 2)

__global__ void __launch_bounds__(128) k_persist(float* __restrict__ out) {
    extern __shared__ __align__(16) unsigned char dyn[];
    uint2*  bFrag = (uint2*)dyn;                   // [ksl 0..15][nb 0..15][lane]
    __half* sAh   = (__half*)(dyn + BFRAG_BYTES);  // [4][64][72]

    const int tid  = threadIdx.x;
    const int warp = tid >> 5, lane = tid & 31;
    const int g = lane >> 2, tg = lane & 3;
    const int cta = blockIdx.x;
    const int grp = cta >> 5;                  // 0,1,2
    const int idx = cta & 31;
    const int nt  = idx >> 2;                  // 0..7
    const int kq  = idx & 3;                   // 0..3
    const int n0  = nt * 128;
    const bool finisher = (kq == 0) && (grp != 1);
    const int layerL = (grp == 0) ? 0 : 1;

    const __half* WT = (grp == 0) ? g_Whh0T : (grp == 1) ? g_Wih1T : g_Whh1T;

    // ---- pack resident weight fragments (once): 16 kslices x 16 nb x 32 lanes
    for (int i = tid; i < 16 * 16 * 32; i += 128) {
        int li  = i & 31;
        int nb  = (i >> 5) & 15;
        int ksl = i >> 9;
        int gi = li >> 2, tgi = li & 3;
        size_t n  = (size_t)(n0 + nb * 8 + gi);
        size_t kb = (size_t)kq * 256 + (size_t)ksl * 16 + tgi * 2;
        uint2 v;
        v.x = *(const uint32_t*)(WT + n * H_ + kb);
        v.y = *(const uint32_t*)(WT + n * H_ + kb + 8);
        bFrag[i] = v;
    }
    __syncthreads();

    for (int t = 0; t < S_; t++) {
        const int p = t & 1;
        const int slot = t & 1;
        const unsigned stamp = (unsigned)t + 1u;
        if (grp == 0 && t == S_ - 1) break;    // layer0: no work at last step

        // ---- 1. wait input hidden ready (8 finisher increments per step) ----
        if (tid == 0) {
            if (grp <= 1) spin_ge((volatile unsigned*)&g_r0, 8u * (unsigned)t);
            else          spin_ge((volatile unsigned*)&g_r1, 8u * (unsigned)t);
            __threadfence();
        }
        __syncthreads();

        // ---- 2. issue all A chunk loads (depth-4 cp.async pipeline) ----
        const __half* Abase = (grp == 2) ? g_h1[p] : g_h0[p];
        const __half* Asrc  = Abase + kq * 256;
#pragma unroll
        for (int c = 0; c < 4; c++) {
#pragma unroll
            for (int it = 0; it < 4; it++) {
                int ii = tid + it * 128;
                int r = ii >> 3, s8 = ii & 7;
                cp_async16(sAh + c * SA_CHUNK + r * SA_STRIDE + s8 * 8,
                           Asrc + (size_t)r * H_ + c * 64 + s8 * 8);
            }
            cp_commit();
        }

        // ---- 3. GEMM: 64(M) x 128(N) x 256(K) ----
        float acc[4][4][4];
#pragma unroll
        for (int a = 0; a < 4; a++)
#pragma unroll
            for (int b = 0; b < 4; b++)
#pragma unroll
                for (int q = 0; q < 4; q++) acc[a][b][q] = 0.f;

#pragma unroll
        for (int c = 0; c < 4; c++) {
            switch (c) {
                case 0: cp_wait<3>(); break;
                case 1: cp_wait<2>(); break;
                case 2: cp_wait<1>(); break;
                default: cp_wait<0>(); break;
            }
            __syncthreads();
            if (c == 3 && tid == 0) {
                // all reads of the input h buffer for THIS step are complete
                if (grp <= 1) atomicAdd(&g_h0rd[p], 1u);
                else          atomicAdd(&g_h1rd[p], 1u);
            }
            const __half* sAb = sAh + c * SA_CHUNK;
#pragma unroll
            for (int kk = 0; kk < 4; kk++) {
                uint32_t af[4][4];
#pragma unroll
                for (int ms = 0; ms < 4; ms++)
                    ldsm4(af[ms], sAb + (ms * 16 + (lane & 15)) * SA_STRIDE
                                      + kk * 16 + (lane >> 4) * 8);
                int kslg = c * 4 + kk;
                uint2 bf[4];
#pragma unroll
                for (int ns = 0; ns < 4; ns++)
                    bf[ns] = bFrag[(kslg * 16 + warp * 4 + ns) * 32 + lane];
#pragma unroll
                for (int ms = 0; ms < 4; ms++)
#pragma unroll
                    for (int ns = 0; ns < 4; ns++)
                        mma16816(acc[ms][ns], af[ms], (const uint32_t*)&bf[ns]);
            }
        }
        __syncthreads();   // protect chunk buffers before next step's cp.async

        float* accumSlot = g_accum[layerL][slot][nt];

        if (!finisher) {
            // ---- producer: red.add partial into accumulator ----
            if (tid == 0 && t >= 2)
                spin_ge(&g_cons[layerL][nt], (unsigned)(t - 1));
            __syncthreads();
#pragma unroll
            for (int ms = 0; ms < 4; ms++)
#pragma unroll
                for (int ns = 0; ns < 4; ns++)
#pragma unroll
                    for (int hh = 0; hh < 2; hh++) {
                        int row = ms * 16 + g + hh * 8;
                        int nl = warp * 32 + ns * 8 + tg * 2;
                        redadd(&accumSlot[row * 128 + nl],     acc[ms][ns][hh * 2]);
                        redadd(&accumSlot[row * 128 + nl + 1], acc[ms][ns][hh * 2 + 1]);
                    }
            __threadfence();
            __syncthreads();
            if (tid == 0) g_flag[cta] = stamp;
        } else {
            // ---- finisher: wait partials + writer-buffer free, then combine ----
            // Writes h[1-p], read last by step t-1 (parity 1-p). Completed reads
            // of that parity through step t-1: ceil(t/2) rounds.
            unsigned rounds = (unsigned)((t + 1) >> 1);
            if (grp == 0) {
                if (tid < 3)       spin_ge(&g_flag[cta + 1 + tid], stamp);
                else if (tid == 3) spin_ge((volatile unsigned*)&g_h0rd[1 - p], 64u * rounds);
            } else {
                if (tid < 3)       spin_ge(&g_flag[cta + 1 + tid], stamp);
                else if (tid < 7)  spin_ge(&g_flag[32 + nt * 4 + (tid - 3)], stamp);
                else if (tid == 7) spin_ge((volatile unsigned*)&g_h1rd[1 - p], 32u * rounds);
            }
            if (tid < 8) __threadfence();
            __syncthreads();

#pragma unroll
            for (int ms = 0; ms < 4; ms++)
#pragma unroll
                for (int ns = 0; ns < 4; ns++)
#pragma unroll
                    for (int hh = 0; hh < 2; hh++) {
                        int row = ms * 16 + g + hh * 8;
                        int nl = warp * 32 + ns * 8 + tg * 2;
                        int n = n0 + nl;
                        float2 q1 = __ldcg((const float2*)&accumSlot[row * 128 + nl]);
                        float sx = acc[ms][ns][hh * 2]     + q1.x;
                        float sy = acc[ms][ns][hh * 2 + 1] + q1.y;
                        __stcg((float2*)&accumSlot[row * 128 + nl], make_float2(0.f, 0.f));
                        if (grp == 0) {
                            size_t xoff = ((size_t)(t + 1) * B_ + row) * H_ + n;
                            float h0a = tanhf(sx + __half2float(g_X0[xoff])     + g_bias0[n]);
                            float h0b = tanhf(sy + __half2float(g_X0[xoff + 1]) + g_bias0[n + 1]);
                            __half2 hv = __floats2half2_rn(h0a, h0b);
                            __stcg((unsigned*)&g_h0[1 - p][row * H_ + n], *(unsigned*)&hv);
                            if (t == S_ - 2) {
                                g_h0f[row * H_ + n]     = h0a;
                                g_h0f[row * H_ + n + 1] = h0b;
                            }
                        } else {
                            float ha = tanhf(sx + g_bias1[n]);
                            float hb = tanhf(sy + g_bias1[n + 1]);
                            __half2 hv = __floats2half2_rn(ha, hb);
                            __stcg((unsigned*)&g_h1[1 - p][row * H_ + n], *(unsigned*)&hv);
                            size_t ooff = ((size_t)row * S_ + t) * H_ + n;
                            out[ooff]     = ha;
                            out[ooff + 1] = hb;
                        }
                    }
            __threadfence();
            __syncthreads();
            if (tid == 0) {
                g_cons[layerL][nt] = stamp;     // slot zeroed + consumed
                if (grp == 0) atomicAdd(&g_r0, 1u);
                else          atomicAdd(&g_r1, 1u);
            }
        }
    }
}

// ---------------- final hidden assembly --------------------------------------
__global__ void k_final(float* __restrict__ out) {
    int i = blockIdx.x * blockDim.x + threadIdx.x;
    if (i < B_ * H_) {
        int b = i >> 10, n = i & 1023;
        size_t base = (size_t)B_ * S_ * H_;
        out[base + i] = g_h0f[i];
        out[base + (size_t)B_ * H_ + i] =
            out[((size_t)b * S_ + (S_ - 1)) * H_ + n];
    }
}

// ---------------- launch ------------------------------------------------------
extern "C" void kernel_launch(void* const* d_in, const int* in_sizes, int n_in,
                              void* d_out, int out_size) {
    (void)in_sizes; (void)n_in; (void)out_size;
    const void*  src  = d_in[0];
    const float* emb  = (const float*)d_in[1];
    const float* Wih0 = (const float*)d_in[2];
    const float* Whh0 = (const float*)d_in[3];
    const float* bih0 = (const float*)d_in[4];
    const float* bhh0 = (const float*)d_in[5];
    const float* Wih1 = (const float*)d_in[6];
    const float* Whh1 = (const float*)d_in[7];
    const float* bih1 = (const float*)d_in[8];
    const float* bhh1 = (const float*)d_in[9];
    float* out = (float*)d_out;

    cudaFuncSetAttribute(k_persist, cudaFuncAttributeMaxDynamicSharedMemorySize, DYN_SMEM);

    // launch order identical to the configuration that survived ncu capture
    k_detect<<<1, 64>>>((const int*)src);                     // 1
    k_convT<<<1024, 256>>>(Wih0, 0);                          // 2
    k_convT<<<1024, 256>>>(Whh0, 1);                          // 3
    k_convT<<<1024, 256>>>(Wih1, 2);                          // 4
    k_convT<<<1024, 256>>>(Whh1, 3);                          // 5
    k_bias<<<4, 256>>>(bih0, bhh0, bih1, bhh1);               // 6
    dim3 g1(16, 512);
    k_phase1<<<g1, 256>>>(src, emb);                          // 7
    k_init<<<(B_ * H_ + 255) / 256, 256>>>();                 // 8
    k_persist<<<NCTA, 128, DYN_SMEM>>>(out);                  // 9
    k_final<<<(B_ * H_ + 255) / 256, 256>>>(out);             // 10
}